// round 2
// baseline (speedup 1.0000x reference)
#include <cuda_runtime.h>

// SparseChannelLinear: y = scatter_rows( (gather_cols(x) @ (W*alpha)^T) ) + bias
// x: [8192, 4096] f32, W: [2048, 2048] f32, bias: [4096] f32,
// active_rows/cols: [2048] int32 (jax default int; sorted, unique).
// out: [8192, 4096] f32.

#define ALPHA_S 0.05f

static constexpr int MT   = 8192;   // B*S
static constexpr int KC   = 2048;   // active input channels (GEMM K)
static constexpr int NR   = 2048;   // active output channels (GEMM N)
static constexpr int FIN  = 4096;
static constexpr int FOUT = 4096;

// scratch: gathered/compacted activations [MT, KC] (67 MB, static device alloc)
__device__ float g_xc[(size_t)MT * KC];

// ---------------------------------------------------------------------------
// Kernel 1: gather active input channels into contiguous compact layout.
// grid (KC/256, MT), block 256. Sorted cols -> ~sequential reads per row.
// ---------------------------------------------------------------------------
__global__ void gather_kernel(const float* __restrict__ x,
                              const int* __restrict__ cols) {
    int j = blockIdx.x * blockDim.x + threadIdx.x;   // compact col
    int m = blockIdx.y;                              // token
    int c = __ldg(&cols[j]);
    g_xc[(size_t)m * KC + j] = __ldg(&x[(size_t)m * FIN + c]);
}

// ---------------------------------------------------------------------------
// Kernel 2: initialize the full output with broadcast bias (covers the
// zero-scatter semantics for inactive rows; active rows overwritten by GEMM).
// ---------------------------------------------------------------------------
__global__ void biasfill_kernel(float4* __restrict__ out,
                                const float4* __restrict__ bias) {
    int i = blockIdx.x * blockDim.x + threadIdx.x;
    out[i] = bias[i & (FOUT / 4 - 1)];
}

// ---------------------------------------------------------------------------
// Kernel 3: fp32 tiled GEMM, C[m][n] = sum_k A[m][k] * W[n][k]
// BM=BN=128, BK=16, 256 threads, 8x8 microtile, register prefetch of the
// next global tile. Epilogue: out[m][active_rows[n]] = alpha*acc + bias[row].
// ---------------------------------------------------------------------------
__global__ __launch_bounds__(256) void gemm_kernel(
    const float* __restrict__ W,
    const float* __restrict__ bias,
    const int* __restrict__ rows,
    float* __restrict__ out)
{
    constexpr int BM = 128, BN = 128, BK = 16;
    __shared__ float As[BK][BM];
    __shared__ float Bs[BK][BN];

    const int tid = threadIdx.x;
    const int tx  = tid & 15;   // n microtile
    const int ty  = tid >> 4;   // m microtile
    const int m0  = blockIdx.y * BM;
    const int n0  = blockIdx.x * BN;

    // global-load mapping: each thread loads 2 float4 per tile for A and B
    const int lrow = tid >> 2;          // 0..63
    const int lcol = (tid & 3) << 2;    // 0,4,8,12

    const float* Ag = g_xc + (size_t)(m0 + lrow) * KC + lcol;
    const float* Bg = W    + (size_t)(n0 + lrow) * KC + lcol;

    float acc[8][8];
    #pragma unroll
    for (int i = 0; i < 8; ++i)
        #pragma unroll
        for (int j = 0; j < 8; ++j) acc[i][j] = 0.f;

    float4 a0 = *(const float4*)(Ag);
    float4 a1 = *(const float4*)(Ag + (size_t)64 * KC);
    float4 b0 = *(const float4*)(Bg);
    float4 b1 = *(const float4*)(Bg + (size_t)64 * KC);

    constexpr int NT = KC / BK;   // 128 k-tiles
    for (int kt = 0; kt < NT; ++kt) {
        // store (transposed) into smem: As[k][m], Bs[k][n]
        As[lcol + 0][lrow]      = a0.x; As[lcol + 1][lrow]      = a0.y;
        As[lcol + 2][lrow]      = a0.z; As[lcol + 3][lrow]      = a0.w;
        As[lcol + 0][lrow + 64] = a1.x; As[lcol + 1][lrow + 64] = a1.y;
        As[lcol + 2][lrow + 64] = a1.z; As[lcol + 3][lrow + 64] = a1.w;
        Bs[lcol + 0][lrow]      = b0.x; Bs[lcol + 1][lrow]      = b0.y;
        Bs[lcol + 2][lrow]      = b0.z; Bs[lcol + 3][lrow]      = b0.w;
        Bs[lcol + 0][lrow + 64] = b1.x; Bs[lcol + 1][lrow + 64] = b1.y;
        Bs[lcol + 2][lrow + 64] = b1.z; Bs[lcol + 3][lrow + 64] = b1.w;
        __syncthreads();

        // prefetch next global tile into registers (overlaps with compute)
        if (kt + 1 < NT) {
            const float* Agn = Ag + (kt + 1) * BK;
            const float* Bgn = Bg + (kt + 1) * BK;
            a0 = *(const float4*)(Agn);
            a1 = *(const float4*)(Agn + (size_t)64 * KC);
            b0 = *(const float4*)(Bgn);
            b1 = *(const float4*)(Bgn + (size_t)64 * KC);
        }

        #pragma unroll
        for (int k = 0; k < BK; ++k) {
            float4 av0 = *(const float4*)&As[k][ty * 8];
            float4 av1 = *(const float4*)&As[k][ty * 8 + 4];
            float4 bv0 = *(const float4*)&Bs[k][tx * 8];
            float4 bv1 = *(const float4*)&Bs[k][tx * 8 + 4];
            float af[8] = {av0.x, av0.y, av0.z, av0.w, av1.x, av1.y, av1.z, av1.w};
            float bf[8] = {bv0.x, bv0.y, bv0.z, bv0.w, bv1.x, bv1.y, bv1.z, bv1.w};
            #pragma unroll
            for (int i = 0; i < 8; ++i)
                #pragma unroll
                for (int j = 0; j < 8; ++j)
                    acc[i][j] = fmaf(af[i], bf[j], acc[i][j]);
        }
        __syncthreads();
    }

    // epilogue: scatter to active output channels with alpha scale + bias
    int   ridx[8];
    float rb[8];
    #pragma unroll
    for (int j = 0; j < 8; ++j) {
        ridx[j] = __ldg(&rows[n0 + tx * 8 + j]);
        rb[j]   = __ldg(&bias[ridx[j]]);
    }
    #pragma unroll
    for (int i = 0; i < 8; ++i) {
        float* orow = out + (size_t)(m0 + ty * 8 + i) * FOUT;
        #pragma unroll
        for (int j = 0; j < 8; ++j)
            orow[ridx[j]] = acc[i][j] * ALPHA_S + rb[j];
    }
}

// ---------------------------------------------------------------------------
extern "C" void kernel_launch(void* const* d_in, const int* in_sizes, int n_in,
                              void* d_out, int out_size) {
    const float* x    = (const float*)d_in[0];
    const float* w    = (const float*)d_in[1];
    const float* bias = (const float*)d_in[2];
    const int*   rows = (const int*)d_in[3];
    const int*   cols = (const int*)d_in[4];
    float*       out  = (float*)d_out;

    // 1) gather active input channels
    gather_kernel<<<dim3(KC / 256, MT), 256>>>(x, cols);
    // 2) fill output with bias (inactive rows keep this value)
    biasfill_kernel<<<(MT * (FOUT / 4)) / 256, 256>>>((float4*)d_out,
                                                      (const float4*)bias);
    // 3) compact GEMM + scatter epilogue
    gemm_kernel<<<dim3(NR / 128, MT / 128), 256>>>(w, bias, rows, out);
}

// round 4
// speedup vs baseline: 2.9768x; 2.9768x over previous
#include <cuda_runtime.h>
#include <cstdint>

// SparseChannelLinear: gather(cols) -> tf32 mma.sync GEMM -> scatter(rows)+bias
// x: [8192,4096] f32, W: [2048,2048] f32, bias: [4096] f32,
// active_rows/cols: [2048] int32. out: [8192,4096] f32.

#define ALPHA_S 0.05f

static constexpr int MT   = 8192;
static constexpr int KC   = 2048;
static constexpr int NR   = 2048;
static constexpr int FIN  = 4096;
static constexpr int FOUT = 4096;

static constexpr int BM = 128, BN = 128, BK = 32;
static constexpr int STAGES  = 3;
static constexpr int KTILES  = KC / BK;          // 64
static constexpr int THREADS = 256;

// smem layout (bytes): rows cache, bias cache, then 3 stages of (A 16K + B 16K)
static constexpr int OFF_ROWS   = 0;      // 128 x int
static constexpr int OFF_BIAS   = 512;    // 128 x float
static constexpr int OFF_TILES  = 1024;
static constexpr int A_BYTES    = BM * BK * 4;            // 16384 (128B per row)
static constexpr int STAGE_BYTES= 2 * A_BYTES;            // 32768
static constexpr int SMEM_TOTAL = OFF_TILES + STAGES * STAGE_BYTES;  // 99328

// scratch (static device allocations)
__device__ float g_xc[(size_t)MT * KC];   // gathered activations, tf32-rounded
__device__ float g_wt[(size_t)NR * KC];   // weights, tf32-rounded

// ---------------------------------------------------------------------------
__device__ __forceinline__ float to_tf32(float v) {
    float r; asm("cvt.rna.tf32.f32 %0, %1;" : "=f"(r) : "f"(v)); return r;
}
__device__ __forceinline__ uint32_t smem_to_u32(const void* p) {
    uint32_t a;
    asm("{ .reg .u64 t; cvta.to.shared.u64 t, %1; cvt.u32.u64 %0, t; }" : "=r"(a) : "l"(p));
    return a;
}
#define CP_ASYNC16(dst, src) \
    asm volatile("cp.async.cg.shared.global [%0], [%1], 16;" :: "r"(dst), "l"(src))
#define CP_COMMIT() asm volatile("cp.async.commit_group;" ::: "memory")
#define CP_WAIT1()  asm volatile("cp.async.wait_group 1;" ::: "memory")

__device__ __forceinline__ void mma_tf32(float* c, const uint32_t* a, const uint32_t* b) {
    asm volatile(
        "mma.sync.aligned.m16n8k8.row.col.f32.tf32.tf32.f32 "
        "{%0,%1,%2,%3}, {%4,%5,%6,%7}, {%8,%9}, {%0,%1,%2,%3};"
        : "+f"(c[0]), "+f"(c[1]), "+f"(c[2]), "+f"(c[3])
        : "r"(a[0]), "r"(a[1]), "r"(a[2]), "r"(a[3]), "r"(b[0]), "r"(b[1]));
}

// element (row, k) inside a 128x32 f32 tile stored with 16B-chunk XOR swizzle:
// byte = row*128 + (chunk(k) ^ (row&7))*16 + (k&3)*4
__device__ __forceinline__ uint32_t tile_addr(int row, int k) {
    return (uint32_t)(row * 128 + ((((k >> 2) & 7) ^ (row & 7)) << 4) + ((k & 3) << 2));
}

// ---------------------------------------------------------------------------
// Kernel 1: gather active input channels, round to tf32, write compact.
__global__ void gather_kernel(const float* __restrict__ x,
                              const int* __restrict__ cols) {
    int j4 = blockIdx.x * blockDim.x + threadIdx.x;
    int m  = blockIdx.y;
    int4 c = *(const int4*)(cols + j4 * 4);
    const float* xr = x + (size_t)m * FIN;
    float4 o;
    o.x = to_tf32(__ldg(xr + c.x));
    o.y = to_tf32(__ldg(xr + c.y));
    o.z = to_tf32(__ldg(xr + c.z));
    o.w = to_tf32(__ldg(xr + c.w));
    *(float4*)(g_xc + (size_t)m * KC + j4 * 4) = o;
}

// Kernel 1b: round weights to tf32 into scratch.
__global__ void wconv_kernel(const float* __restrict__ w) {
    size_t i = ((size_t)blockIdx.x * blockDim.x + threadIdx.x) * 4;
    float4 v = *(const float4*)(w + i);
    float4 o = { to_tf32(v.x), to_tf32(v.y), to_tf32(v.z), to_tf32(v.w) };
    *(float4*)(g_wt + i) = o;
}

// Kernel 2: out = broadcast(bias) everywhere (inactive rows keep it).
__global__ void biasfill_kernel(float4* __restrict__ out,
                                const float4* __restrict__ bias) {
    int i = blockIdx.x * blockDim.x + threadIdx.x;
    out[i] = bias[i & (FOUT / 4 - 1)];
}

// ---------------------------------------------------------------------------
// Kernel 3: tf32 mma.sync GEMM. C[m][n] = sum_k A[m][k]*W[n][k].
// 256 threads, warp grid 2(m) x 4(n), warp tile 64x32, 3-stage cp.async.
// Epilogue: out[m][active_rows[n]] = alpha*acc + bias[row].
__global__ __launch_bounds__(THREADS, 2) void gemm_kernel(
    const float* __restrict__ bias,
    const int* __restrict__ rows,
    float* __restrict__ out)
{
    extern __shared__ char smem[];
    const uint32_t sbase = smem_to_u32(smem);
    const int tid = threadIdx.x;
    const int wid = tid >> 5;
    const int lid = tid & 31;
    const int n0 = blockIdx.x * BN;
    const int m0 = blockIdx.y * BM;

    int*   srows = (int*)(smem + OFF_ROWS);
    float* sbias = (float*)(smem + OFF_BIAS);
    if (tid < 128) {
        int r = __ldg(&rows[n0 + tid]);
        srows[tid] = r;
        sbias[tid] = __ldg(&bias[r]);
    }

    // async stage fill: 2048 16B chunks (A:1024, B:1024), 8 per thread
    auto refill = [&](int kt, int s) {
        const uint32_t stg = sbase + OFF_TILES + s * STAGE_BYTES;
        #pragma unroll
        for (int i = 0; i < 8; ++i) {
            int c   = tid + i * THREADS;
            int isB = c >= 1024;
            int cc  = c & 1023;
            int row = cc >> 3;
            int ch  = cc & 7;
            uint32_t dst = stg + (isB ? A_BYTES : 0) + row * 128 +
                           ((ch ^ (row & 7)) << 4);
            const float* src = isB
                ? (g_wt + (size_t)(n0 + row) * KC + kt * BK + ch * 4)
                : (g_xc + (size_t)(m0 + row) * KC + kt * BK + ch * 4);
            CP_ASYNC16(dst, src);
        }
    };

    refill(0, 0); CP_COMMIT();
    refill(1, 1); CP_COMMIT();

    const int wm = (wid & 1) * 64;   // warp m offset
    const int wn = (wid >> 1) * 32;  // warp n offset
    const int lr = lid >> 2;         // lane row (0..7)
    const int lc = lid & 3;          // lane col (0..3)

    float acc[4][4][4];
    #pragma unroll
    for (int mt = 0; mt < 4; ++mt)
        #pragma unroll
        for (int nt = 0; nt < 4; ++nt)
            #pragma unroll
            for (int i = 0; i < 4; ++i) acc[mt][nt][i] = 0.f;

    for (int kt = 0; kt < KTILES; ++kt) {
        const int s = kt % STAGES;
        CP_WAIT1();
        __syncthreads();
        if (kt + 2 < KTILES) refill(kt + 2, (kt + 2) % STAGES);
        CP_COMMIT();

        const uint32_t* At = (const uint32_t*)(smem + OFF_TILES + s * STAGE_BYTES);
        const uint32_t* Bt = (const uint32_t*)(smem + OFF_TILES + s * STAGE_BYTES + A_BYTES);

        #pragma unroll
        for (int k8 = 0; k8 < BK / 8; ++k8) {
            const int k0 = k8 * 8;
            uint32_t a[4][4], b[4][2];
            #pragma unroll
            for (int mt = 0; mt < 4; ++mt) {
                int m = wm + mt * 16 + lr;
                a[mt][0] = At[tile_addr(m,     k0 + lc)     >> 2];
                a[mt][1] = At[tile_addr(m + 8, k0 + lc)     >> 2];
                a[mt][2] = At[tile_addr(m,     k0 + lc + 4) >> 2];
                a[mt][3] = At[tile_addr(m + 8, k0 + lc + 4) >> 2];
            }
            #pragma unroll
            for (int nt = 0; nt < 4; ++nt) {
                int n = wn + nt * 8 + lr;
                b[nt][0] = Bt[tile_addr(n, k0 + lc)     >> 2];
                b[nt][1] = Bt[tile_addr(n, k0 + lc + 4) >> 2];
            }
            #pragma unroll
            for (int mt = 0; mt < 4; ++mt)
                #pragma unroll
                for (int nt = 0; nt < 4; ++nt)
                    mma_tf32(acc[mt][nt], a[mt], b[nt]);
        }
        __syncthreads();
    }

    // epilogue: scatter alpha*acc + bias to active output channels
    #pragma unroll
    for (int mt = 0; mt < 4; ++mt) {
        int mA = m0 + wm + mt * 16 + lr;
        int mB = mA + 8;
        float* rowA = out + (size_t)mA * FOUT;
        float* rowB = out + (size_t)mB * FOUT;
        #pragma unroll
        for (int nt = 0; nt < 4; ++nt) {
            int nloc = wn + nt * 8 + lc * 2;
            int r0 = srows[nloc], r1 = srows[nloc + 1];
            float b0 = sbias[nloc], b1 = sbias[nloc + 1];
            rowA[r0] = acc[mt][nt][0] * ALPHA_S + b0;
            rowA[r1] = acc[mt][nt][1] * ALPHA_S + b1;
            rowB[r0] = acc[mt][nt][2] * ALPHA_S + b0;
            rowB[r1] = acc[mt][nt][3] * ALPHA_S + b1;
        }
    }
}

// ---------------------------------------------------------------------------
extern "C" void kernel_launch(void* const* d_in, const int* in_sizes, int n_in,
                              void* d_out, int out_size) {
    const float* x    = (const float*)d_in[0];
    const float* w    = (const float*)d_in[1];
    const float* bias = (const float*)d_in[2];
    const int*   rows = (const int*)d_in[3];
    const int*   cols = (const int*)d_in[4];
    float*       out  = (float*)d_out;

    cudaFuncSetAttribute(gemm_kernel, cudaFuncAttributeMaxDynamicSharedMemorySize,
                         SMEM_TOTAL);

    gather_kernel<<<dim3(KC / (128 * 4), MT), 128>>>(x, cols);
    wconv_kernel<<<(NR * KC / 4) / 256, 256>>>(w);
    biasfill_kernel<<<((size_t)MT * FOUT / 4) / 256, 256>>>((float4*)d_out,
                                                            (const float4*)bias);
    gemm_kernel<<<dim3(NR / BN, MT / BM), THREADS, SMEM_TOTAL>>>(bias, rows, out);
}

// round 6
// speedup vs baseline: 3.8171x; 1.2823x over previous
#include <cuda_runtime.h>
#include <cstdint>

// SparseChannelLinear: gather(cols) -> tf32 mma.sync GEMM (fragment-packed
// operands) -> scatter(rows)+bias.
// x: [8192,4096] f32, W: [2048,2048] f32, bias: [4096] f32,
// active_rows/cols: [2048] int32. out: [8192,4096] f32.

#define ALPHA_S 0.05f

static constexpr int MT   = 8192;
static constexpr int KC   = 2048;
static constexpr int NR   = 2048;
static constexpr int FIN  = 4096;
static constexpr int FOUT = 4096;

static constexpr int BM = 128, BN = 128, BK = 32;
static constexpr int STAGES  = 3;
static constexpr int KTILES  = KC / BK;          // 64
static constexpr int THREADS = 256;

static constexpr int K8S = KC / 8;               // 256 k8-atoms total

// smem: rows cache, bias cache, then 3 stages of (A 16K + B 16K)
static constexpr int OFF_ROWS    = 0;      // 128 x int
static constexpr int OFF_BIAS    = 512;    // 128 x float
static constexpr int OFF_TILES   = 1024;
static constexpr int A_BYTES     = BM * BK * 4;           // 16384
static constexpr int STAGE_BYTES = 2 * A_BYTES;           // 32768
static constexpr int SMEM_TOTAL  = OFF_TILES + STAGES * STAGE_BYTES;  // 99328

// scratch, fragment-packed for mma.m16n8k8.tf32:
// g_xc: A fragments. [m_atom(512)][k8(256)][lane(32)] x float4
//       lane quad = { A(m1,c1), A(m1+8,c1), A(m1,c1+4), A(m1+8,c1+4) }
// g_wt: B fragments. [n_atom(256)][k8(256)][lane(32)] x float2
//       lane pair = { W(n,k), W(n,k+4) }
__device__ float g_xc[(size_t)MT * KC];
__device__ float g_wt[(size_t)NR * KC];

// ---------------------------------------------------------------------------
__device__ __forceinline__ float to_tf32(float v) {
    float r; asm("cvt.rna.tf32.f32 %0, %1;" : "=f"(r) : "f"(v)); return r;
}
__device__ __forceinline__ uint32_t smem_to_u32(const void* p) {
    uint32_t a;
    asm("{ .reg .u64 t; cvta.to.shared.u64 t, %1; cvt.u32.u64 %0, t; }" : "=r"(a) : "l"(p));
    return a;
}
#define CP_ASYNC16(dst, src) \
    asm volatile("cp.async.cg.shared.global [%0], [%1], 16;" :: "r"(dst), "l"(src))
#define CP_COMMIT() asm volatile("cp.async.commit_group;" ::: "memory")
#define CP_WAIT1()  asm volatile("cp.async.wait_group 1;" ::: "memory")

#define LDS128(r, addr) \
    asm volatile("ld.shared.v4.b32 {%0,%1,%2,%3}, [%4];" \
        : "=r"((r)[0]), "=r"((r)[1]), "=r"((r)[2]), "=r"((r)[3]) : "r"(addr))
#define LDS64(r, addr) \
    asm volatile("ld.shared.v2.b32 {%0,%1}, [%2];" \
        : "=r"((r)[0]), "=r"((r)[1]) : "r"(addr))

__device__ __forceinline__ void mma_tf32(float* c, const uint32_t* a, const uint32_t* b) {
    asm volatile(
        "mma.sync.aligned.m16n8k8.row.col.f32.tf32.tf32.f32 "
        "{%0,%1,%2,%3}, {%4,%5,%6,%7}, {%8,%9}, {%0,%1,%2,%3};"
        : "+f"(c[0]), "+f"(c[1]), "+f"(c[2]), "+f"(c[3])
        : "r"(a[0]), "r"(a[1]), "r"(a[2]), "r"(a[3]), "r"(b[0]), "r"(b[1]));
}

// ---------------------------------------------------------------------------
// Kernel 1: gather active input channels into A-fragment-packed layout.
// one thread = one (m_atom, k8, lane) -> one float4 (16B) coalesced write.
__global__ void gather_kernel(const float* __restrict__ x,
                              const int* __restrict__ cols) {
    int t = blockIdx.x * blockDim.x + threadIdx.x;
    int lane   = t & 31;
    int k8     = (t >> 5) & (K8S - 1);
    int m_atom = t >> 13;
    int lr = lane >> 2, lc = lane & 3;
    int c1 = __ldg(&cols[k8 * 8 + lc]);
    int c2 = __ldg(&cols[k8 * 8 + lc + 4]);
    const float* r1 = x + (size_t)(m_atom * 16 + lr) * FIN;
    const float* r2 = r1 + (size_t)8 * FIN;
    float4 o = { to_tf32(__ldg(r1 + c1)), to_tf32(__ldg(r2 + c1)),
                 to_tf32(__ldg(r1 + c2)), to_tf32(__ldg(r2 + c2)) };
    ((float4*)g_xc)[t] = o;
}

// Kernel 1b: weights -> tf32, B-fragment-packed layout.
__global__ void wconv_kernel(const float* __restrict__ w) {
    int t = blockIdx.x * blockDim.x + threadIdx.x;
    int lane   = t & 31;
    int k8     = (t >> 5) & (K8S - 1);
    int n_atom = t >> 13;
    const float* wr = w + (size_t)(n_atom * 8 + (lane >> 2)) * KC + k8 * 8 + (lane & 3);
    float2 o = { to_tf32(__ldg(wr)), to_tf32(__ldg(wr + 4)) };
    ((float2*)g_wt)[t] = o;
}

// Kernel 2: out = broadcast(bias) everywhere (inactive rows keep it).
__global__ void biasfill_kernel(float4* __restrict__ out,
                                const float4* __restrict__ bias) {
    int i = blockIdx.x * blockDim.x + threadIdx.x;
    out[i] = bias[i & (FOUT / 4 - 1)];
}

// ---------------------------------------------------------------------------
// Kernel 3: tf32 mma.sync GEMM with fragment-packed smem (no swizzle, pure
// vector LDS). 8 warps (2m x 4n), warp tile 64x32, 3-stage cp.async pipeline.
__global__ __launch_bounds__(THREADS, 2) void gemm_kernel(
    const float* __restrict__ bias,
    const int* __restrict__ rows,
    float* __restrict__ out)
{
    extern __shared__ char smem[];
    const uint32_t sbase = smem_to_u32(smem);
    const int tid = threadIdx.x;
    const int wid = tid >> 5;
    const int lid = tid & 31;
    const int n0 = blockIdx.x * BN;
    const int m0 = blockIdx.y * BM;

    int*   srows = (int*)(smem + OFF_ROWS);
    float* sbias = (float*)(smem + OFF_BIAS);
    if (tid < 128) {
        int r = __ldg(&rows[n0 + tid]);
        srows[tid] = r;
        sbias[tid] = __ldg(&bias[r]);
    }

    // stage fill: 2048 16B chunks (A:1024 then B:1024), smem dst is linear.
    auto refill = [&](int kt, int s) {
        const uint32_t stg = sbase + OFF_TILES + s * STAGE_BYTES;
        #pragma unroll
        for (int i = 0; i < 8; ++i) {
            int c = tid + i * THREADS;
            uint32_t dst = stg + c * 16;
            const float4* src;
            if (c < 1024) {                 // A: atom = m_atom_l*4 + k8_l
                int atom = c >> 5, lane = c & 31;
                int m_atom_g = (m0 >> 4) + (atom >> 2);
                int k8_g     = kt * 4 + (atom & 3);
                src = (const float4*)g_xc + ((size_t)m_atom_g * K8S + k8_g) * 32 + lane;
            } else {                        // B: atom = n_atom_l*4 + k8_l
                int cc = c - 1024;
                int atom = cc >> 4, pair = cc & 15;
                int n_atom_g = (n0 >> 3) + (atom >> 2);
                int k8_g     = kt * 4 + (atom & 3);
                // g_wt is float2-packed: one (n_atom,k8) block = 32 lanes
                // x 8B = 256B = 16 float4 chunks.
                src = (const float4*)g_wt + ((size_t)n_atom_g * K8S + k8_g) * 16 + pair;
            }
            CP_ASYNC16(dst, (const void*)src);
        }
    };

    refill(0, 0); CP_COMMIT();
    refill(1, 1); CP_COMMIT();

    const int ma = (wid & 1) * 4;    // warp m-atom base (m offset 0/64)
    const int nb = (wid >> 1) * 4;   // warp n-atom base (n offset 0/32/64/96)
    const int lr = lid >> 2;
    const int lc = lid & 3;

    float acc[4][4][4];
    #pragma unroll
    for (int mt = 0; mt < 4; ++mt)
        #pragma unroll
        for (int nt = 0; nt < 4; ++nt)
            #pragma unroll
            for (int i = 0; i < 4; ++i) acc[mt][nt][i] = 0.f;

    for (int kt = 0; kt < KTILES; ++kt) {
        const int s = kt % STAGES;
        CP_WAIT1();
        __syncthreads();
        if (kt + 2 < KTILES) refill(kt + 2, (kt + 2) % STAGES);
        CP_COMMIT();

        const uint32_t stg   = sbase + OFF_TILES + s * STAGE_BYTES;
        const uint32_t aW    = stg + lid * 16;            // + atom*512
        const uint32_t bW    = stg + A_BYTES + lid * 8;   // + atom*256

        #pragma unroll
        for (int k8 = 0; k8 < 4; ++k8) {
            uint32_t a[4][4], b[4][2];
            #pragma unroll
            for (int mt = 0; mt < 4; ++mt)
                LDS128(a[mt], aW + ((ma + mt) * 4 + k8) * 512);
            #pragma unroll
            for (int nt = 0; nt < 4; ++nt)
                LDS64(b[nt], bW + ((nb + nt) * 4 + k8) * 256);
            #pragma unroll
            for (int mt = 0; mt < 4; ++mt)
                #pragma unroll
                for (int nt = 0; nt < 4; ++nt)
                    mma_tf32(acc[mt][nt], a[mt], b[nt]);
        }
        __syncthreads();
    }

    // epilogue: scatter alpha*acc + bias to active output channels
    #pragma unroll
    for (int mt = 0; mt < 4; ++mt) {
        int mA = m0 + (ma + mt) * 16 + lr;
        float* rowA = out + (size_t)mA * FOUT;
        float* rowB = rowA + (size_t)8 * FOUT;
        #pragma unroll
        for (int nt = 0; nt < 4; ++nt) {
            int nloc = (nb + nt) * 8 + lc * 2;
            int r0 = srows[nloc], r1 = srows[nloc + 1];
            float b0 = sbias[nloc], b1 = sbias[nloc + 1];
            rowA[r0] = acc[mt][nt][0] * ALPHA_S + b0;
            rowA[r1] = acc[mt][nt][1] * ALPHA_S + b1;
            rowB[r0] = acc[mt][nt][2] * ALPHA_S + b0;
            rowB[r1] = acc[mt][nt][3] * ALPHA_S + b1;
        }
    }
}

// ---------------------------------------------------------------------------
extern "C" void kernel_launch(void* const* d_in, const int* in_sizes, int n_in,
                              void* d_out, int out_size) {
    const float* x    = (const float*)d_in[0];
    const float* w    = (const float*)d_in[1];
    const float* bias = (const float*)d_in[2];
    const int*   rows = (const int*)d_in[3];
    const int*   cols = (const int*)d_in[4];
    float*       out  = (float*)d_out;

    cudaFuncSetAttribute(gemm_kernel, cudaFuncAttributeMaxDynamicSharedMemorySize,
                         SMEM_TOTAL);

    gather_kernel<<<(MT / 16) * K8S * 32 / 256, 256>>>(x, cols);
    wconv_kernel<<<(NR / 8) * K8S * 32 / 256, 256>>>(w);
    biasfill_kernel<<<((size_t)MT * FOUT / 4) / 256, 256>>>((float4*)d_out,
                                                            (const float4*)bias);
    gemm_kernel<<<dim3(NR / BN, MT / BM), THREADS, SMEM_TOTAL>>>(bias, rows, out);
}

// round 7
// speedup vs baseline: 3.9431x; 1.0330x over previous
#include <cuda_runtime.h>
#include <cstdint>

// SparseChannelLinear: gather(cols) -> tf32 mma.sync GEMM (fragment-packed
// operands, 64x64 warp tile) -> scatter(rows)+bias.

#define ALPHA_S 0.05f

static constexpr int MT   = 8192;
static constexpr int KC   = 2048;
static constexpr int NR   = 2048;
static constexpr int FIN  = 4096;
static constexpr int FOUT = 4096;

static constexpr int BM = 128, BN = 128, BK = 32;
static constexpr int STAGES  = 3;
static constexpr int KTILES  = KC / BK;          // 64
static constexpr int THREADS = 128;              // 4 warps, 2x2 grid of 64x64 tiles

static constexpr int K8S = KC / 8;               // 256 k8-atoms total

// smem: rows cache, bias cache, then 3 stages of (A 16K + B 16K)
static constexpr int OFF_ROWS    = 0;      // 128 x int
static constexpr int OFF_BIAS    = 512;    // 128 x float
static constexpr int OFF_TILES   = 1024;
static constexpr int A_BYTES     = BM * BK * 4;           // 16384
static constexpr int STAGE_BYTES = 2 * A_BYTES;           // 32768
static constexpr int SMEM_TOTAL  = OFF_TILES + STAGES * STAGE_BYTES;  // 99328

// scratch, fragment-packed for mma.m16n8k8.tf32:
// g_xc: A fragments. [m_atom(512)][k8(256)][lane(32)] x float4
//       lane quad = { A(m1,c1), A(m1+8,c1), A(m1,c1+4), A(m1+8,c1+4) }
// g_wt: B fragments (alpha-folded). [n_atom(256)][k8(256)][lane(32)] x float2
//       lane pair = { aW(n,k), aW(n,k+4) }
__device__ float g_xc[(size_t)MT * KC];
__device__ float g_wt[(size_t)NR * KC];

// ---------------------------------------------------------------------------
__device__ __forceinline__ float to_tf32(float v) {
    float r; asm("cvt.rna.tf32.f32 %0, %1;" : "=f"(r) : "f"(v)); return r;
}
__device__ __forceinline__ uint32_t smem_to_u32(const void* p) {
    uint32_t a;
    asm("{ .reg .u64 t; cvta.to.shared.u64 t, %1; cvt.u32.u64 %0, t; }" : "=r"(a) : "l"(p));
    return a;
}
#define CP_ASYNC16(dst, src) \
    asm volatile("cp.async.cg.shared.global [%0], [%1], 16;" :: "r"(dst), "l"(src))
#define CP_COMMIT() asm volatile("cp.async.commit_group;" ::: "memory")
#define CP_WAIT1()  asm volatile("cp.async.wait_group 1;" ::: "memory")

#define LDS128(r, addr) \
    asm volatile("ld.shared.v4.b32 {%0,%1,%2,%3}, [%4];" \
        : "=r"((r)[0]), "=r"((r)[1]), "=r"((r)[2]), "=r"((r)[3]) : "r"(addr))
#define LDS64(r, addr) \
    asm volatile("ld.shared.v2.b32 {%0,%1}, [%2];" \
        : "=r"((r)[0]), "=r"((r)[1]) : "r"(addr))

__device__ __forceinline__ void mma_tf32(float* c, const uint32_t* a, const uint32_t* b) {
    asm volatile(
        "mma.sync.aligned.m16n8k8.row.col.f32.tf32.tf32.f32 "
        "{%0,%1,%2,%3}, {%4,%5,%6,%7}, {%8,%9}, {%0,%1,%2,%3};"
        : "+f"(c[0]), "+f"(c[1]), "+f"(c[2]), "+f"(c[3])
        : "r"(a[0]), "r"(a[1]), "r"(a[2]), "r"(a[3]), "r"(b[0]), "r"(b[1]));
}

// ---------------------------------------------------------------------------
// Kernel 1: gather active input channels into A-fragment-packed layout.
__global__ void gather_kernel(const float* __restrict__ x,
                              const int* __restrict__ cols) {
    int t = blockIdx.x * blockDim.x + threadIdx.x;
    int lane   = t & 31;
    int k8     = (t >> 5) & (K8S - 1);
    int m_atom = t >> 13;
    int lr = lane >> 2, lc = lane & 3;
    int c1 = __ldg(&cols[k8 * 8 + lc]);
    int c2 = __ldg(&cols[k8 * 8 + lc + 4]);
    const float* r1 = x + (size_t)(m_atom * 16 + lr) * FIN;
    const float* r2 = r1 + (size_t)8 * FIN;
    float4 o = { to_tf32(__ldg(r1 + c1)), to_tf32(__ldg(r2 + c1)),
                 to_tf32(__ldg(r1 + c2)), to_tf32(__ldg(r2 + c2)) };
    ((float4*)g_xc)[t] = o;
}

// Kernel 1b: weights -> alpha-folded tf32, B-fragment-packed layout.
__global__ void wconv_kernel(const float* __restrict__ w) {
    int t = blockIdx.x * blockDim.x + threadIdx.x;
    int lane   = t & 31;
    int k8     = (t >> 5) & (K8S - 1);
    int n_atom = t >> 13;
    const float* wr = w + (size_t)(n_atom * 8 + (lane >> 2)) * KC + k8 * 8 + (lane & 3);
    float2 o = { to_tf32(__ldg(wr) * ALPHA_S), to_tf32(__ldg(wr + 4) * ALPHA_S) };
    ((float2*)g_wt)[t] = o;
}

// Kernel 2: out = broadcast(bias) everywhere (inactive rows keep it).
__global__ void biasfill_kernel(float4* __restrict__ out,
                                const float4* __restrict__ bias) {
    int i = blockIdx.x * blockDim.x + threadIdx.x;
    out[i] = bias[i & (FOUT / 4 - 1)];
}

// ---------------------------------------------------------------------------
// Kernel 3: tf32 mma.sync GEMM. 4 warps (2m x 2n), warp tile 64x64,
// fragment-packed smem (pure vector LDS), 3-stage cp.async pipeline.
__global__ __launch_bounds__(THREADS, 2) void gemm_kernel(
    const float* __restrict__ bias,
    const int* __restrict__ rows,
    float* __restrict__ out)
{
    extern __shared__ char smem[];
    const uint32_t sbase = smem_to_u32(smem);
    const int tid = threadIdx.x;
    const int wid = tid >> 5;
    const int lid = tid & 31;
    const int n0 = blockIdx.x * BN;
    const int m0 = blockIdx.y * BM;

    int*   srows = (int*)(smem + OFF_ROWS);
    float* sbias = (float*)(smem + OFF_BIAS);
    {
        int r = __ldg(&rows[n0 + tid]);
        srows[tid] = r;
        sbias[tid] = __ldg(&bias[r]);
    }

    // stage fill: 2048 16B chunks (A:1024 then B:1024), 16 per thread.
    auto refill = [&](int kt, int s) {
        const uint32_t stg = sbase + OFF_TILES + s * STAGE_BYTES;
        #pragma unroll
        for (int i = 0; i < 16; ++i) {
            int c = tid + i * THREADS;
            uint32_t dst = stg + c * 16;
            const float4* src;
            if (c < 1024) {                 // A: atom = m_atom_l*4 + k8_l
                int atom = c >> 5, lane = c & 31;
                int m_atom_g = (m0 >> 4) + (atom >> 2);
                int k8_g     = kt * 4 + (atom & 3);
                src = (const float4*)g_xc + ((size_t)m_atom_g * K8S + k8_g) * 32 + lane;
            } else {                        // B: atom = n_atom_l*4 + k8_l
                int cc = c - 1024;
                int atom = cc >> 4, pair = cc & 15;
                int n_atom_g = (n0 >> 3) + (atom >> 2);
                int k8_g     = kt * 4 + (atom & 3);
                // g_wt float2-packed: one (n_atom,k8) block = 256B = 16 float4
                src = (const float4*)g_wt + ((size_t)n_atom_g * K8S + k8_g) * 16 + pair;
            }
            CP_ASYNC16(dst, (const void*)src);
        }
    };

    refill(0, 0); CP_COMMIT();
    refill(1, 1); CP_COMMIT();

    const int ma = (wid & 1) * 4;    // warp m-atom base (4 atoms = 64 rows)
    const int nb = (wid >> 1) * 8;   // warp n-atom base (8 atoms = 64 cols)
    const int lr = lid >> 2;
    const int lc = lid & 3;

    float acc[4][8][4];
    #pragma unroll
    for (int mt = 0; mt < 4; ++mt)
        #pragma unroll
        for (int nt = 0; nt < 8; ++nt)
            #pragma unroll
            for (int i = 0; i < 4; ++i) acc[mt][nt][i] = 0.f;

    for (int kt = 0; kt < KTILES; ++kt) {
        const int s = kt % STAGES;
        CP_WAIT1();
        __syncthreads();
        if (kt + 2 < KTILES) refill(kt + 2, (kt + 2) % STAGES);
        CP_COMMIT();

        const uint32_t stg = sbase + OFF_TILES + s * STAGE_BYTES;
        const uint32_t aW  = stg + lid * 16;            // + atom*512
        const uint32_t bW  = stg + A_BYTES + lid * 8;   // + atom*256

        #pragma unroll
        for (int k8 = 0; k8 < 4; ++k8) {
            uint32_t a[4][4], b[8][2];
            #pragma unroll
            for (int mt = 0; mt < 4; ++mt)
                LDS128(a[mt], aW + ((ma + mt) * 4 + k8) * 512);
            #pragma unroll
            for (int nt = 0; nt < 8; ++nt)
                LDS64(b[nt], bW + ((nb + nt) * 4 + k8) * 256);
            #pragma unroll
            for (int mt = 0; mt < 4; ++mt)
                #pragma unroll
                for (int nt = 0; nt < 8; ++nt)
                    mma_tf32(acc[mt][nt], a[mt], b[nt]);
        }
        __syncthreads();
    }

    // epilogue: scatter acc + bias to active output channels (alpha folded in W)
    #pragma unroll
    for (int mt = 0; mt < 4; ++mt) {
        int mA = m0 + (ma + mt) * 16 + lr;
        float* rowA = out + (size_t)mA * FOUT;
        float* rowB = rowA + (size_t)8 * FOUT;
        #pragma unroll
        for (int nt = 0; nt < 8; ++nt) {
            int nloc = (nb + nt) * 8 + lc * 2;
            int r0 = srows[nloc], r1 = srows[nloc + 1];
            float b0 = sbias[nloc], b1 = sbias[nloc + 1];
            rowA[r0] = acc[mt][nt][0] + b0;
            rowA[r1] = acc[mt][nt][1] + b1;
            rowB[r0] = acc[mt][nt][2] + b0;
            rowB[r1] = acc[mt][nt][3] + b1;
        }
    }
}

// ---------------------------------------------------------------------------
extern "C" void kernel_launch(void* const* d_in, const int* in_sizes, int n_in,
                              void* d_out, int out_size) {
    const float* x    = (const float*)d_in[0];
    const float* w    = (const float*)d_in[1];
    const float* bias = (const float*)d_in[2];
    const int*   rows = (const int*)d_in[3];
    const int*   cols = (const int*)d_in[4];
    float*       out  = (float*)d_out;

    cudaFuncSetAttribute(gemm_kernel, cudaFuncAttributeMaxDynamicSharedMemorySize,
                         SMEM_TOTAL);

    gather_kernel<<<(MT / 16) * K8S * 32 / 256, 256>>>(x, cols);
    wconv_kernel<<<(NR / 8) * K8S * 32 / 256, 256>>>(w);
    biasfill_kernel<<<((size_t)MT * FOUT / 4) / 256, 256>>>((float4*)d_out,
                                                            (const float4*)bias);
    gemm_kernel<<<dim3(NR / BN, MT / BM), THREADS, SMEM_TOTAL>>>(bias, rows, out);
}

// round 8
// speedup vs baseline: 6.2143x; 1.5760x over previous
#include <cuda_runtime.h>
#include <cuda_fp16.h>
#include <cstdint>

// SparseChannelLinear: gather(cols)+fp16 -> fp16 mma.sync m16n8k16 GEMM
// (fragment-packed operands, 64x64 warp tile) -> scatter(rows)+bias.
// fp16 has the same 10-bit mantissa as tf32 -> same accuracy, 2x throughput.

#define ALPHA_S 0.05f

static constexpr int MT   = 8192;
static constexpr int KC   = 2048;
static constexpr int NR   = 2048;
static constexpr int FIN  = 4096;
static constexpr int FOUT = 4096;

static constexpr int BM = 128, BN = 128, BK = 64;   // BK in elements (4 k16-atoms)
static constexpr int STAGES  = 3;
static constexpr int KTILES  = KC / BK;             // 32
static constexpr int THREADS = 128;                 // 4 warps, 2x2 of 64x64 tiles

static constexpr int K16S = KC / 16;                // 128 k16-atoms total

// smem: rows cache, bias cache, then 3 stages of (A 16K + B 16K)
static constexpr int OFF_ROWS    = 0;      // 128 x int
static constexpr int OFF_BIAS    = 512;    // 128 x float
static constexpr int OFF_TILES   = 1024;
static constexpr int A_BYTES     = BM * BK * 2;           // 16384
static constexpr int STAGE_BYTES = 2 * A_BYTES;           // 32768
static constexpr int SMEM_TOTAL  = OFF_TILES + STAGES * STAGE_BYTES;  // 99328

// scratch, fragment-packed for mma.m16n8k16.f16:
// g_xc: A fragments. [m_atom(512)][k16(128)][lane(32)] x uint4 (= regs a0..a3)
//   a0={(r,c0),(r,c1)} a1={(r+8,c0),(r+8,c1)} a2={(r,c2),(r,c3)} a3={(r+8,c2),(r+8,c3)}
//   where r = m_atom*16 + lane/4, c0..c3 = cols[k16*16 + {2lc,2lc+1,2lc+8,2lc+9}]
// g_wt: B fragments (alpha-folded). [n_atom(256)][k16(128)][lane(32)] x uint2
//   b0={(2lc,n),(2lc+1,n)} b1={(2lc+8,n),(2lc+9,n)}, n = n_atom*8 + lane/4
__device__ uint4 g_xc[(size_t)(MT / 16) * K16S * 32];
__device__ uint2 g_wt[(size_t)(NR / 8) * K16S * 32];

// ---------------------------------------------------------------------------
__device__ __forceinline__ uint32_t smem_to_u32(const void* p) {
    uint32_t a;
    asm("{ .reg .u64 t; cvta.to.shared.u64 t, %1; cvt.u32.u64 %0, t; }" : "=r"(a) : "l"(p));
    return a;
}
__device__ __forceinline__ uint32_t pack_h2(float lo, float hi) {
    __half2 h = __floats2half2_rn(lo, hi);
    return *reinterpret_cast<uint32_t*>(&h);
}
#define CP_ASYNC16(dst, src) \
    asm volatile("cp.async.cg.shared.global [%0], [%1], 16;" :: "r"(dst), "l"(src))
#define CP_COMMIT() asm volatile("cp.async.commit_group;" ::: "memory")
#define CP_WAIT1()  asm volatile("cp.async.wait_group 1;" ::: "memory")

#define LDS128(r, addr) \
    asm volatile("ld.shared.v4.b32 {%0,%1,%2,%3}, [%4];" \
        : "=r"((r)[0]), "=r"((r)[1]), "=r"((r)[2]), "=r"((r)[3]) : "r"(addr))
#define LDS64(r, addr) \
    asm volatile("ld.shared.v2.b32 {%0,%1}, [%2];" \
        : "=r"((r)[0]), "=r"((r)[1]) : "r"(addr))

__device__ __forceinline__ void mma_f16(float* c, const uint32_t* a, const uint32_t* b) {
    asm volatile(
        "mma.sync.aligned.m16n8k16.row.col.f32.f16.f16.f32 "
        "{%0,%1,%2,%3}, {%4,%5,%6,%7}, {%8,%9}, {%0,%1,%2,%3};"
        : "+f"(c[0]), "+f"(c[1]), "+f"(c[2]), "+f"(c[3])
        : "r"(a[0]), "r"(a[1]), "r"(a[2]), "r"(a[3]), "r"(b[0]), "r"(b[1]));
}

// ---------------------------------------------------------------------------
// Kernel 1: gather active input channels into fp16 A-fragment-packed layout.
// one thread = one (m_atom, k16, lane) -> one uint4 (16B) coalesced write.
__global__ void gather_kernel(const float* __restrict__ x,
                              const int* __restrict__ cols) {
    int t = blockIdx.x * blockDim.x + threadIdx.x;
    int lane   = t & 31;
    int k16    = (t >> 5) & (K16S - 1);
    int m_atom = t >> 12;
    int lr = lane >> 2, lc = lane & 3;
    const int* cb = cols + k16 * 16;
    int c0 = __ldg(cb + 2 * lc);
    int c1 = __ldg(cb + 2 * lc + 1);
    int c2 = __ldg(cb + 2 * lc + 8);
    int c3 = __ldg(cb + 2 * lc + 9);
    const float* r1 = x + (size_t)(m_atom * 16 + lr) * FIN;
    const float* r2 = r1 + (size_t)8 * FIN;
    uint4 o;
    o.x = pack_h2(__ldg(r1 + c0), __ldg(r1 + c1));
    o.y = pack_h2(__ldg(r2 + c0), __ldg(r2 + c1));
    o.z = pack_h2(__ldg(r1 + c2), __ldg(r1 + c3));
    o.w = pack_h2(__ldg(r2 + c2), __ldg(r2 + c3));
    g_xc[t] = o;
}

// Kernel 1b: weights -> alpha-folded fp16, B-fragment-packed layout.
__global__ void wconv_kernel(const float* __restrict__ w) {
    int t = blockIdx.x * blockDim.x + threadIdx.x;
    int lane   = t & 31;
    int k16    = (t >> 5) & (K16S - 1);
    int n_atom = t >> 12;
    const float* wr = w + (size_t)(n_atom * 8 + (lane >> 2)) * KC
                        + k16 * 16 + 2 * (lane & 3);
    uint2 o;
    o.x = pack_h2(__ldg(wr)     * ALPHA_S, __ldg(wr + 1) * ALPHA_S);
    o.y = pack_h2(__ldg(wr + 8) * ALPHA_S, __ldg(wr + 9) * ALPHA_S);
    g_wt[t] = o;
}

// Kernel 2: out = broadcast(bias) everywhere (inactive rows keep it).
__global__ void biasfill_kernel(float4* __restrict__ out,
                                const float4* __restrict__ bias) {
    int i = blockIdx.x * blockDim.x + threadIdx.x;
    out[i] = bias[i & (FOUT / 4 - 1)];
}

// ---------------------------------------------------------------------------
// Kernel 3: fp16 mma.sync GEMM. 4 warps (2m x 2n), warp tile 64x64,
// fragment-packed smem (pure vector LDS), 3-stage cp.async pipeline, BK=64.
__global__ __launch_bounds__(THREADS, 2) void gemm_kernel(
    const float* __restrict__ bias,
    const int* __restrict__ rows,
    float* __restrict__ out)
{
    extern __shared__ char smem[];
    const uint32_t sbase = smem_to_u32(smem);
    const int tid = threadIdx.x;
    const int wid = tid >> 5;
    const int lid = tid & 31;
    const int n0 = blockIdx.x * BN;
    const int m0 = blockIdx.y * BM;

    int*   srows = (int*)(smem + OFF_ROWS);
    float* sbias = (float*)(smem + OFF_BIAS);
    {
        int r = __ldg(&rows[n0 + tid]);
        srows[tid] = r;
        sbias[tid] = __ldg(&bias[r]);
    }

    // stage fill: 2048 16B chunks (A:1024 then B:1024), 16 per thread.
    auto refill = [&](int kt, int s) {
        const uint32_t stg = sbase + OFF_TILES + s * STAGE_BYTES;
        #pragma unroll
        for (int i = 0; i < 16; ++i) {
            int c = tid + i * THREADS;
            uint32_t dst = stg + c * 16;
            const void* src;
            if (c < 1024) {                 // A: atom = m_atom_l*4 + k16_l
                int atom = c >> 5, lane = c & 31;
                int m_atom_g = (m0 >> 4) + (atom >> 2);
                int k16_g    = kt * 4 + (atom & 3);
                src = (const void*)(g_xc + ((size_t)m_atom_g * K16S + k16_g) * 32 + lane);
            } else {                        // B: atom = n_atom_l*4 + k16_l
                int cc = c - 1024;
                int atom = cc >> 4, pair = cc & 15;
                int n_atom_g = (n0 >> 3) + (atom >> 2);
                int k16_g    = kt * 4 + (atom & 3);
                // g_wt uint2-packed: one (n_atom,k16) block = 256B = 16 x 16B
                src = (const void*)((const uint4*)g_wt +
                      ((size_t)n_atom_g * K16S + k16_g) * 16 + pair);
            }
            CP_ASYNC16(dst, src);
        }
    };

    refill(0, 0); CP_COMMIT();
    refill(1, 1); CP_COMMIT();

    const int ma = (wid & 1) * 4;    // warp m-atom base (4 atoms = 64 rows)
    const int nb = (wid >> 1) * 8;   // warp n-atom base (8 atoms = 64 cols)
    const int lr = lid >> 2;
    const int lc = lid & 3;

    float acc[4][8][4];
    #pragma unroll
    for (int mt = 0; mt < 4; ++mt)
        #pragma unroll
        for (int nt = 0; nt < 8; ++nt)
            #pragma unroll
            for (int i = 0; i < 4; ++i) acc[mt][nt][i] = 0.f;

    for (int kt = 0; kt < KTILES; ++kt) {
        const int s = kt % STAGES;
        CP_WAIT1();
        __syncthreads();
        if (kt + 2 < KTILES) refill(kt + 2, (kt + 2) % STAGES);
        CP_COMMIT();

        const uint32_t stg = sbase + OFF_TILES + s * STAGE_BYTES;
        const uint32_t aW  = stg + lid * 16;            // + atom*512
        const uint32_t bW  = stg + A_BYTES + lid * 8;   // + atom*256

        #pragma unroll
        for (int k16 = 0; k16 < 4; ++k16) {
            uint32_t a[4][4], b[8][2];
            #pragma unroll
            for (int mt = 0; mt < 4; ++mt)
                LDS128(a[mt], aW + ((ma + mt) * 4 + k16) * 512);
            #pragma unroll
            for (int nt = 0; nt < 8; ++nt)
                LDS64(b[nt], bW + ((nb + nt) * 4 + k16) * 256);
            #pragma unroll
            for (int mt = 0; mt < 4; ++mt)
                #pragma unroll
                for (int nt = 0; nt < 8; ++nt)
                    mma_f16(acc[mt][nt], a[mt], b[nt]);
        }
        __syncthreads();
    }

    // epilogue: scatter acc + bias to active output channels (alpha folded in W)
    #pragma unroll
    for (int mt = 0; mt < 4; ++mt) {
        int mA = m0 + (ma + mt) * 16 + lr;
        float* rowA = out + (size_t)mA * FOUT;
        float* rowB = rowA + (size_t)8 * FOUT;
        #pragma unroll
        for (int nt = 0; nt < 8; ++nt) {
            int nloc = (nb + nt) * 8 + lc * 2;
            int r0 = srows[nloc], r1 = srows[nloc + 1];
            float b0 = sbias[nloc], b1 = sbias[nloc + 1];
            rowA[r0] = acc[mt][nt][0] + b0;
            rowA[r1] = acc[mt][nt][1] + b1;
            rowB[r0] = acc[mt][nt][2] + b0;
            rowB[r1] = acc[mt][nt][3] + b1;
        }
    }
}

// ---------------------------------------------------------------------------
extern "C" void kernel_launch(void* const* d_in, const int* in_sizes, int n_in,
                              void* d_out, int out_size) {
    const float* x    = (const float*)d_in[0];
    const float* w    = (const float*)d_in[1];
    const float* bias = (const float*)d_in[2];
    const int*   rows = (const int*)d_in[3];
    const int*   cols = (const int*)d_in[4];
    float*       out  = (float*)d_out;

    cudaFuncSetAttribute(gemm_kernel, cudaFuncAttributeMaxDynamicSharedMemorySize,
                         SMEM_TOTAL);

    gather_kernel<<<(MT / 16) * K16S * 32 / 256, 256>>>(x, cols);
    wconv_kernel<<<(NR / 8) * K16S * 32 / 256, 256>>>(w);
    biasfill_kernel<<<((size_t)MT * FOUT / 4) / 256, 256>>>((float4*)d_out,
                                                            (const float4*)bias);
    gemm_kernel<<<dim3(NR / BN, MT / BM), THREADS, SMEM_TOTAL>>>(bias, rows, out);
}